// round 12
// baseline (speedup 1.0000x reference)
#include <cuda_runtime.h>
#include <cuda_bf16.h>
#include <cstdint>

#define B_ 8
#define C_ 256
#define H_ 128
#define W_ 128
#define NEL (B_*C_*H_*W_)

// Scratch (no allocation allowed -> __device__ globals)
__device__ __nv_bfloat16 g_whi[3 * C_ * C_];   // weight hi, K-major [o][c]
__device__ __nv_bfloat16 g_wlo[3 * C_ * C_];   // weight lo
__device__ __nv_bfloat16 g_t0h[NEL];           // dw-out hi/lo per chain, [b][h][w][c]
__device__ __nv_bfloat16 g_t0l[NEL];
__device__ __nv_bfloat16 g_t1h[NEL];
__device__ __nv_bfloat16 g_t1l[NEL];
__device__ __nv_bfloat16 g_t2h[NEL];
__device__ __nv_bfloat16 g_t2l[NEL];
__device__ __nv_bfloat16 g_qhi[NEL];           // q hi, [b][h][c][w]
__device__ __nv_bfloat16 g_qlo[NEL];
__device__ __nv_bfloat16 g_khi[NEL];           // k hi, [b][h][c][w]
__device__ __nv_bfloat16 g_klo[NEL];
__device__ __nv_bfloat16 g_vhi[NEL];           // v hi, [b][h][w][c]
__device__ __nv_bfloat16 g_vlo[NEL];

// ---- cp.async helpers ----
__device__ __forceinline__ uint32_t saddr(const void* p) {
    return (uint32_t)__cvta_generic_to_shared(p);
}
__device__ __forceinline__ void cp16(uint32_t dst, const void* src) {
    asm volatile("cp.async.cg.shared.global [%0], [%1], 16;" :: "r"(dst), "l"(src));
}
#define CP_COMMIT asm volatile("cp.async.commit_group;")
#define CP_WAIT0  asm volatile("cp.async.wait_group 0;")
#define CP_WAIT1  asm volatile("cp.async.wait_group 1;")

// ---- mma.sync / ldmatrix helpers (plain sm_103 features) ----
__device__ __forceinline__ void ldmx4(uint32_t* r, uint32_t addr) {
    asm volatile("ldmatrix.sync.aligned.m8n8.x4.shared.b16 {%0,%1,%2,%3}, [%4];"
                 : "=r"(r[0]), "=r"(r[1]), "=r"(r[2]), "=r"(r[3]) : "r"(addr));
}
__device__ __forceinline__ void mma16816(float* d, const uint32_t* a, const uint32_t* b) {
    asm volatile(
        "mma.sync.aligned.m16n8k16.row.col.f32.bf16.bf16.f32 "
        "{%0,%1,%2,%3}, {%4,%5,%6,%7}, {%8,%9}, {%0,%1,%2,%3};"
        : "+f"(d[0]), "+f"(d[1]), "+f"(d[2]), "+f"(d[3])
        : "r"(a[0]), "r"(a[1]), "r"(a[2]), "r"(a[3]), "r"(b[0]), "r"(b[1]));
}
__device__ __forceinline__ void split_bf16(float x, __nv_bfloat16& h, __nv_bfloat16& l) {
    h = __float2bfloat16_rn(x);
    l = __float2bfloat16_rn(x - __bfloat162float(h));
}

// ---------------------------------------------------------------------------
// Merged weight split: {q,k,v} pw weights fp32 -> hi/lo bf16. One launch.
// ---------------------------------------------------------------------------
__global__ void wsplit_kernel(const float* __restrict__ qpw,
                              const float* __restrict__ kpw,
                              const float* __restrict__ vpw,
                              __nv_bfloat16* __restrict__ hi,
                              __nv_bfloat16* __restrict__ lo)
{
    int i = blockIdx.x * 256 + threadIdx.x;
    int chain = i / (C_ * C_), j = i % (C_ * C_);
    const float* W = (chain == 0) ? qpw : (chain == 1) ? kpw : vpw;
    split_bf16(W[j], hi[i], lo[i]);
}

// ---------------------------------------------------------------------------
// MERGED fused depthwise 3x3 + bias + transpose + bf16 split (unchanged R11).
// ---------------------------------------------------------------------------
#define DSP 132
__global__ __launch_bounds__(256) void dwsplit_kernel(
    const float* __restrict__ hidden, const float* __restrict__ ctx,
    const float* __restrict__ qdw, const float* __restrict__ qdb,
    const float* __restrict__ kdw, const float* __restrict__ kdb,
    const float* __restrict__ vdw, const float* __restrict__ vdb,
    __nv_bfloat16* __restrict__ t0h, __nv_bfloat16* __restrict__ t0l,
    __nv_bfloat16* __restrict__ t1h, __nv_bfloat16* __restrict__ t1l,
    __nv_bfloat16* __restrict__ t2h, __nv_bfloat16* __restrict__ t2l)
{
    __shared__ float S[32 * DSP];
    const int c0 = blockIdx.x * 32;
    const int h = blockIdx.y;
    const int zz = blockIdx.z;
    const int chain = zz % 3, b = zz / 3;
    const float* x    = (chain == 0) ? hidden : ctx;
    const float* wgt  = (chain == 0) ? qdw : (chain == 1) ? kdw : vdw;
    const float* bias = (chain == 0) ? qdb : (chain == 1) ? kdb : vdb;
    __nv_bfloat16* hi = (chain == 0) ? t0h : (chain == 1) ? t1h : t2h;
    __nv_bfloat16* lo = (chain == 0) ? t0l : (chain == 1) ? t1l : t2l;

    const int tid = threadIdx.x;
    const int tx = tid & 31, ty = tid >> 5;
    const int w0 = tx * 4;

    #pragma unroll
    for (int j = 0; j < 4; j++) {
        const int cc = ty + j * 8;
        const int c = c0 + cc;
        const float* wc = wgt + c * 9;
        const float* plane = x + (b * C_ + c) * (H_ * W_);
        float bv = __ldg(&bias[c]);
        float4 acc = make_float4(bv, bv, bv, bv);
        #pragma unroll
        for (int i = 0; i < 3; i++) {
            int hh = h + i - 1;
            if (hh < 0 || hh >= H_) continue;
            float4 xc = __ldg((const float4*)(plane + hh * W_ + w0));
            float xl = __shfl_up_sync(0xffffffffu, xc.w, 1);
            float xr = __shfl_down_sync(0xffffffffu, xc.x, 1);
            if (tx == 0)  xl = 0.f;
            if (tx == 31) xr = 0.f;
            float wl = __ldg(&wc[i*3+0]), wm = __ldg(&wc[i*3+1]), wr = __ldg(&wc[i*3+2]);
            acc.x += wl*xl   + wm*xc.x + wr*xc.y;
            acc.y += wl*xc.x + wm*xc.y + wr*xc.z;
            acc.z += wl*xc.y + wm*xc.z + wr*xc.w;
            acc.w += wl*xc.z + wm*xc.w + wr*xr;
        }
        *(float4*)&S[cc * DSP + w0] = acc;
    }
    __syncthreads();

    const int w = tid & 127;
    const int cb = (tid >> 7) * 16;
    __nv_bfloat16 hb[16], lb[16];
    #pragma unroll
    for (int e = 0; e < 16; e++)
        split_bf16(S[(cb + e) * DSP + w], hb[e], lb[e]);
    size_t idx = ((size_t)(b * H_ + h) * W_ + w) * C_ + c0 + cb;
    *(uint4*)(hi + idx)     = *(uint4*)&hb[0];
    *(uint4*)(hi + idx + 8) = *(uint4*)&hb[8];
    *(uint4*)(lo + idx)     = *(uint4*)&lb[0];
    *(uint4*)(lo + idx + 8) = *(uint4*)&lb[8];
}

// ---------------------------------------------------------------------------
// MERGED pointwise 1x1 split-bf16 mma.sync GEMM (unchanged R11).
// ---------------------------------------------------------------------------
#define MP2 72
#define PWT (128*MP2)
#define PW_STG (4*PWT)
#define PWS_SMEM (2*PW_STG*2)

__global__ __launch_bounds__(256, 1) void pw_mma_kernel(
    const __nv_bfloat16* __restrict__ t0h, const __nv_bfloat16* __restrict__ t0l,
    const __nv_bfloat16* __restrict__ t1h, const __nv_bfloat16* __restrict__ t1l,
    const __nv_bfloat16* __restrict__ t2h, const __nv_bfloat16* __restrict__ t2l,
    const __nv_bfloat16* __restrict__ whi_b, const __nv_bfloat16* __restrict__ wlo_b,
    const float* __restrict__ qpb, const float* __restrict__ kpb, const float* __restrict__ vpb,
    __nv_bfloat16* __restrict__ q_hi, __nv_bfloat16* __restrict__ q_lo,
    __nv_bfloat16* __restrict__ k_hi, __nv_bfloat16* __restrict__ k_lo,
    __nv_bfloat16* __restrict__ v_hi, __nv_bfloat16* __restrict__ v_lo)
{
    extern __shared__ char psm[];
    const uint32_t sbase = saddr(psm);
    const int chain = blockIdx.x >> 1;
    const int o0 = (blockIdx.x & 1) * 128;
    const int h = blockIdx.y, b = blockIdx.z;
    const int bh = b * H_ + h;
    const int tid = threadIdx.x;
    const int wid = tid >> 5, lane = tid & 31;
    const int m0 = (wid >> 2) * 64;
    const int n0 = (wid & 3) * 32;

    const __nv_bfloat16* thi = (chain == 0) ? t0h : (chain == 1) ? t1h : t2h;
    const __nv_bfloat16* tlo = (chain == 0) ? t0l : (chain == 1) ? t1l : t2l;
    const __nv_bfloat16* whi = whi_b + (size_t)chain * (C_ * C_);
    const __nv_bfloat16* wlo = wlo_b + (size_t)chain * (C_ * C_);
    const float* bias = (chain == 0) ? qpb : (chain == 1) ? kpb : vpb;
    __nv_bfloat16* ohi = (chain == 0) ? q_hi : (chain == 1) ? k_hi : v_hi;
    __nv_bfloat16* olo = (chain == 0) ? q_lo : (chain == 1) ? k_lo : v_lo;

    float d[4][4][4];
    #pragma unroll
    for (int mi = 0; mi < 4; mi++)
        #pragma unroll
        for (int ni = 0; ni < 4; ni++)
            { d[mi][ni][0]=0.f; d[mi][ni][1]=0.f; d[mi][ni][2]=0.f; d[mi][ni][3]=0.f; }

    int a_off[4], b_off[2];
    #pragma unroll
    for (int mi = 0; mi < 4; mi++)
        a_off[mi] = (m0 + mi*16 + (lane & 15)) * MP2 + (lane >> 4) * 8;
    #pragma unroll
    for (int p = 0; p < 2; p++) {
        int tl = lane >> 3;
        b_off[p] = (n0 + p*16 + (tl >> 1)*8 + (lane & 7)) * MP2 + (tl & 1) * 8;
    }

    const __nv_bfloat16* tbh = thi + (size_t)bh * (W_ * C_);
    const __nv_bfloat16* tbl = tlo + (size_t)bh * (W_ * C_);
    const int rl = tid >> 3, c8 = (tid & 7) * 8;

    #define PW_STAGE_LOAD(ch, sbuf) do { \
        const int kk_ = (ch) * 64; \
        uint32_t base_ = sbase + (uint32_t)(sbuf) * (PW_STG * 2); \
        _Pragma("unroll") \
        for (int rr = 0; rr < 4; rr++) { \
            int r = rl + rr * 32; \
            uint32_t doff = (uint32_t)(r * MP2 + c8) * 2; \
            cp16(base_ + 0*PWT*2 + doff, whi + (o0 + r) * C_ + kk_ + c8); \
            cp16(base_ + 1*PWT*2 + doff, wlo + (o0 + r) * C_ + kk_ + c8); \
            cp16(base_ + 2*PWT*2 + doff, tbh + r * C_ + kk_ + c8); \
            cp16(base_ + 3*PWT*2 + doff, tbl + r * C_ + kk_ + c8); \
        } } while (0)

    PW_STAGE_LOAD(0, 0); CP_COMMIT;

    for (int ch = 0; ch < 4; ch++) {
        if (ch < 3) { PW_STAGE_LOAD(ch + 1, (ch + 1) & 1); CP_COMMIT; CP_WAIT1; }
        else        { CP_WAIT0; }
        __syncthreads();
        const uint32_t sb0 = sbase + (uint32_t)(ch & 1) * (PW_STG * 2);

        #pragma unroll
        for (int ks = 0; ks < 4; ks++) {
            const int k0 = ks * 16;
            uint32_t ah[4][4], al[4][4], bh2[2][4], bl2[2][4];
            #pragma unroll
            for (int mi = 0; mi < 4; mi++) {
                ldmx4(ah[mi], sb0 + (a_off[mi] + k0) * 2);
                ldmx4(al[mi], sb0 + (PWT + a_off[mi] + k0) * 2);
            }
            #pragma unroll
            for (int p = 0; p < 2; p++) {
                ldmx4(bh2[p], sb0 + (2*PWT + b_off[p] + k0) * 2);
                ldmx4(bl2[p], sb0 + (3*PWT + b_off[p] + k0) * 2);
            }
            #pragma unroll
            for (int mi = 0; mi < 4; mi++)
                #pragma unroll
                for (int ni = 0; ni < 4; ni++)
                    mma16816(d[mi][ni], ah[mi], &bh2[ni >> 1][(ni & 1) * 2]);
            #pragma unroll
            for (int mi = 0; mi < 4; mi++)
                #pragma unroll
                for (int ni = 0; ni < 4; ni++)
                    mma16816(d[mi][ni], ah[mi], &bl2[ni >> 1][(ni & 1) * 2]);
            #pragma unroll
            for (int mi = 0; mi < 4; mi++)
                #pragma unroll
                for (int ni = 0; ni < 4; ni++)
                    mma16816(d[mi][ni], al[mi], &bh2[ni >> 1][(ni & 1) * 2]);
        }
        __syncthreads();
    }
    #undef PW_STAGE_LOAD

    if (chain != 2) {
        #pragma unroll
        for (int mi = 0; mi < 4; mi++) {
            int o1 = o0 + m0 + mi*16 + (lane >> 2);
            float bv1 = __ldg(&bias[o1]);
            float bv2 = __ldg(&bias[o1 + 8]);
            size_t r1 = ((size_t)bh * C_ + o1) * W_;
            size_t r2 = r1 + 8 * W_;
            #pragma unroll
            for (int ni = 0; ni < 4; ni++) {
                int wc = n0 + ni*8 + (lane & 3)*2;
                __nv_bfloat162 hp, lp;
                split_bf16(d[mi][ni][0] + bv1, hp.x, lp.x);
                split_bf16(d[mi][ni][1] + bv1, hp.y, lp.y);
                *(__nv_bfloat162*)(ohi + r1 + wc) = hp;
                *(__nv_bfloat162*)(olo + r1 + wc) = lp;
                split_bf16(d[mi][ni][2] + bv2, hp.x, lp.x);
                split_bf16(d[mi][ni][3] + bv2, hp.y, lp.y);
                *(__nv_bfloat162*)(ohi + r2 + wc) = hp;
                *(__nv_bfloat162*)(olo + r2 + wc) = lp;
            }
        }
    } else {
        __syncthreads();
        float* DS = (float*)psm;
        #pragma unroll
        for (int mi = 0; mi < 4; mi++) {
            int m_ = m0 + mi*16 + (lane >> 2);
            #pragma unroll
            for (int ni = 0; ni < 4; ni++) {
                int n_ = n0 + ni*8 + (lane & 3)*2;
                DS[n_*132 + m_]         = d[mi][ni][0];
                DS[(n_+1)*132 + m_]     = d[mi][ni][1];
                DS[n_*132 + m_ + 8]     = d[mi][ni][2];
                DS[(n_+1)*132 + m_ + 8] = d[mi][ni][3];
            }
        }
        __syncthreads();
        for (int i = tid; i < 128*32; i += 256) {
            int w = i >> 5, o4 = (i & 31) * 4;
            float4 v = *(float4*)&DS[w*132 + o4];
            float4 bv = *(const float4*)&bias[o0 + o4];
            size_t idx = ((size_t)bh * W_ + w) * C_ + o0 + o4;
            __nv_bfloat162 h01, h23, l01, l23;
            split_bf16(v.x + bv.x, h01.x, l01.x);
            split_bf16(v.y + bv.y, h01.y, l01.y);
            split_bf16(v.z + bv.z, h23.x, l23.x);
            split_bf16(v.w + bv.w, h23.y, l23.y);
            *(__nv_bfloat162*)(ohi + idx)     = h01;
            *(__nv_bfloat162*)(ohi + idx + 2) = h23;
            *(__nv_bfloat162*)(olo + idx)     = l01;
            *(__nv_bfloat162*)(olo + idx + 2) = l23;
        }
    }
}

// ---------------------------------------------------------------------------
// Attention, 512 threads / 16 warps: warp grid 8(m) x 2(n-half).
// Each warp: 16 rows x 64 cols of the 128-wide chunk -> s[8][4], o[8][4]
// (64 accum regs).  Softmax row stats combined across warp pairs via smem.
// ---------------------------------------------------------------------------
#define AMP 136
#define AQHI 0
#define AQLO (128*AMP)
#define AKVHI (2*128*AMP)
#define AKVLO (3*128*AMP)
#define APHI (4*128*AMP)
#define APLO (5*128*AMP)
#define APMX (6*128*AMP)               // bf16-elem offset; pm/ps floats live here
#define ATT_SMEM (6*128*AMP*2 + 2048)

__global__ __launch_bounds__(512, 1) void attn_mma_kernel(
    const __nv_bfloat16* __restrict__ qhi, const __nv_bfloat16* __restrict__ qlo,
    const __nv_bfloat16* __restrict__ khi, const __nv_bfloat16* __restrict__ klo,
    const __nv_bfloat16* __restrict__ vhi, const __nv_bfloat16* __restrict__ vlo,
    float* __restrict__ out)
{
    extern __shared__ char smraw[];
    const uint32_t sb = saddr(smraw);
    float* pm = (float*)(smraw + (size_t)APMX * 2);   // [2][128] partial max
    float* ps = pm + 256;                              // [2][128] partial sum
    const int r0 = blockIdx.x * 128;
    const int h = blockIdx.y, b = blockIdx.z;
    const int bh = b * H_ + h;
    const size_t bho = (size_t)bh * (C_ * W_);
    const int tid = threadIdx.x;
    const int wid = tid >> 5, lane = tid & 31;
    const int m0 = (wid >> 1) * 16;      // warp row tile
    const int nh = wid & 1;              // warp n-half (0/1 -> cols nh*64..+64)
    const float scale = 0.17677669529663687f;

    const int a_off = (m0 + (lane & 15)) * AMP + (lane >> 4) * 8;
    int b_off[4];
    {
        int tl = lane >> 3;
        #pragma unroll
        for (int p = 0; p < 4; p++)
            b_off[p] = (nh*64 + p*16 + (tl >> 1)*8 + (lane & 7)) * AMP + (tl & 1) * 8;
    }
    const int ra = m0 + (lane >> 2);
    const int rb = ra + 8;
    const int pcol0 = (lane & 3) * 2;

    const int rl = tid >> 4, c8 = (tid & 15) * 8;    // 32 rows/pass, 4 passes
    #define ALOAD(dstbase, src, rlen, roff, coff) do { \
        _Pragma("unroll") \
        for (int j = 0; j < 4; j++) { \
            int r = rl + j * 32; \
            cp16(sb + ((dstbase) + r * AMP + c8) * 2, \
                 (src) + ((size_t)((roff) + r)) * (rlen) + (coff) + c8); \
        } } while (0)

    float o[8][4];
    #pragma unroll
    for (int nt = 0; nt < 8; nt++) { o[nt][0]=0.f; o[nt][1]=0.f; o[nt][2]=0.f; o[nt][3]=0.f; }
    float m_a = -1e30f, m_b = -1e30f, l_a = 0.f, l_b = 0.f;

    ALOAD(AQHI,  qhi + bho, W_, r0, 0);
    ALOAD(AQLO,  qlo + bho, W_, r0, 0);
    ALOAD(AKVHI, khi + bho, W_, 0, 0);
    ALOAD(AKVLO, klo + bho, W_, 0, 0);
    CP_COMMIT; CP_WAIT0; __syncthreads();

    for (int dt = 0; dt < 2; dt++) {
        // ---- S = Q K^T chunk (warp covers its 64 d-cols) ----
        float s[8][4];
        #pragma unroll
        for (int nt = 0; nt < 8; nt++) { s[nt][0]=0.f; s[nt][1]=0.f; s[nt][2]=0.f; s[nt][3]=0.f; }
        #pragma unroll
        for (int kw = 0; kw < 8; kw++) {
            uint32_t qh[4], ql[4];
            ldmx4(qh, sb + (AQHI + a_off + kw*16) * 2);
            ldmx4(ql, sb + (AQLO + a_off + kw*16) * 2);
            #pragma unroll
            for (int bg = 0; bg < 2; bg++) {
                uint32_t bh0[4], bh1[4], bl0[4], bl1[4];
                ldmx4(bh0, sb + (AKVHI + b_off[bg*2]   + kw*16) * 2);
                ldmx4(bh1, sb + (AKVHI + b_off[bg*2+1] + kw*16) * 2);
                ldmx4(bl0, sb + (AKVLO + b_off[bg*2]   + kw*16) * 2);
                ldmx4(bl1, sb + (AKVLO + b_off[bg*2+1] + kw*16) * 2);
                float* s4 = &s[bg*4][0];
                mma16816(s4+0,  qh, &bh0[0]); mma16816(s4+4,  qh, &bh0[2]);
                mma16816(s4+8,  qh, &bh1[0]); mma16816(s4+12, qh, &bh1[2]);
                mma16816(s4+0,  qh, &bl0[0]); mma16816(s4+4,  qh, &bl0[2]);
                mma16816(s4+8,  qh, &bl1[0]); mma16816(s4+12, qh, &bl1[2]);
                mma16816(s4+0,  ql, &bh0[0]); mma16816(s4+4,  ql, &bh0[2]);
                mma16816(s4+8,  ql, &bh1[0]); mma16816(s4+12, ql, &bh1[2]);
            }
        }
        __syncthreads();                      // K buffer fully consumed
        ALOAD(AKVHI, vhi + bho, C_, 0, dt*128);   // prefetch V (overlaps softmax)
        ALOAD(AKVLO, vlo + bho, C_, 0, dt*128);
        CP_COMMIT;

        // ---- online softmax, cross-warp-pair combine ----
        #pragma unroll
        for (int nt = 0; nt < 8; nt++) {
            s[nt][0] *= scale; s[nt][1] *= scale; s[nt][2] *= scale; s[nt][3] *= scale;
        }
        float mc_a = -1e30f, mc_b = -1e30f;
        #pragma unroll
        for (int nt = 0; nt < 8; nt++) {
            mc_a = fmaxf(mc_a, fmaxf(s[nt][0], s[nt][1]));
            mc_b = fmaxf(mc_b, fmaxf(s[nt][2], s[nt][3]));
        }
        mc_a = fmaxf(mc_a, __shfl_xor_sync(0xffffffffu, mc_a, 1));
        mc_a = fmaxf(mc_a, __shfl_xor_sync(0xffffffffu, mc_a, 2));
        mc_b = fmaxf(mc_b, __shfl_xor_sync(0xffffffffu, mc_b, 1));
        mc_b = fmaxf(mc_b, __shfl_xor_sync(0xffffffffu, mc_b, 2));
        if ((lane & 3) == 0) { pm[nh*128 + ra] = mc_a; pm[nh*128 + rb] = mc_b; }
        __syncthreads();
        float m_na = fmaxf(m_a, fmaxf(mc_a, pm[(nh^1)*128 + ra]));
        float m_nb = fmaxf(m_b, fmaxf(mc_b, pm[(nh^1)*128 + rb]));
        float ca = __expf(m_a - m_na), cb = __expf(m_b - m_nb);
        float la_c = 0.f, lb_c = 0.f;
        #pragma unroll
        for (int nt = 0; nt < 8; nt++) {
            float e0 = __expf(s[nt][0] - m_na), e1 = __expf(s[nt][1] - m_na);
            float e2 = __expf(s[nt][2] - m_nb), e3 = __expf(s[nt][3] - m_nb);
            la_c += e0 + e1; lb_c += e2 + e3;
            int col = nh*64 + nt*8 + pcol0;
            __nv_bfloat162 hp, lp;
            split_bf16(e0, hp.x, lp.x); split_bf16(e1, hp.y, lp.y);
            *(__nv_bfloat162*)(smraw + (APHI + ra*AMP + col)*2) = hp;
            *(__nv_bfloat162*)(smraw + (APLO + ra*AMP + col)*2) = lp;
            split_bf16(e2, hp.x, lp.x); split_bf16(e3, hp.y, lp.y);
            *(__nv_bfloat162*)(smraw + (APHI + rb*AMP + col)*2) = hp;
            *(__nv_bfloat162*)(smraw + (APLO + rb*AMP + col)*2) = lp;
            o[nt][0] *= ca; o[nt][1] *= ca; o[nt][2] *= cb; o[nt][3] *= cb;
        }
        la_c += __shfl_xor_sync(0xffffffffu, la_c, 1);
        la_c += __shfl_xor_sync(0xffffffffu, la_c, 2);
        lb_c += __shfl_xor_sync(0xffffffffu, lb_c, 1);
        lb_c += __shfl_xor_sync(0xffffffffu, lb_c, 2);
        if ((lane & 3) == 0) { ps[nh*128 + ra] = la_c; ps[nh*128 + rb] = lb_c; }
        __syncthreads();
        l_a = l_a * ca + la_c + ps[(nh^1)*128 + ra];
        l_b = l_b * cb + lb_c + ps[(nh^1)*128 + rb];
        m_a = m_na;  m_b = m_nb;
        CP_WAIT0; __syncthreads();            // V ready; P visible to all warps

        // ---- O += P V chunk (warp covers its 64 w-cols) ----
        #pragma unroll
        for (int kw = 0; kw < 8; kw++) {
            uint32_t ph[4], pl[4];
            ldmx4(ph, sb + (APHI + a_off + kw*16) * 2);
            ldmx4(pl, sb + (APLO + a_off + kw*16) * 2);
            #pragma unroll
            for (int bg = 0; bg < 2; bg++) {
                uint32_t bh0[4], bh1[4], bl0[4], bl1[4];
                ldmx4(bh0, sb + (AKVHI + b_off[bg*2]   + kw*16) * 2);
                ldmx4(bh1, sb + (AKVHI + b_off[bg*2+1] + kw*16) * 2);
                ldmx4(bl0, sb + (AKVLO + b_off[bg*2]   + kw*16) * 2);
                ldmx4(bl1, sb + (AKVLO + b_off[bg*2+1] + kw*16) * 2);
                float* o4 = &o[bg*4][0];
                mma16816(o4+0,  ph, &bh0[0]); mma16816(o4+4,  ph, &bh0[2]);
                mma16816(o4+8,  ph, &bh1[0]); mma16816(o4+12, ph, &bh1[2]);
                mma16816(o4+0,  ph, &bl0[0]); mma16816(o4+4,  ph, &bl0[2]);
                mma16816(o4+8,  ph, &bl1[0]); mma16816(o4+12, ph, &bl1[2]);
                mma16816(o4+0,  pl, &bh0[0]); mma16816(o4+4,  pl, &bh0[2]);
                mma16816(o4+8,  pl, &bh1[0]); mma16816(o4+12, pl, &bh1[2]);
            }
        }

        if (dt == 0) {
            __syncthreads();                  // V consumed; reload K chunk 1
            ALOAD(AKVHI, khi + bho, W_, 128, 0);
            ALOAD(AKVLO, klo + bho, W_, 128, 0);
            CP_COMMIT; CP_WAIT0; __syncthreads();
        }
    }
    #undef ALOAD

    // ---- epilogue ----
    float inva = 1.f / l_a, invb = 1.f / l_b;
    __syncthreads();
    float* OS = (float*)(smraw + (size_t)APHI * 2);
    #pragma unroll
    for (int nt = 0; nt < 8; nt++) {
        int col = nh*64 + nt*8 + pcol0;
        *(float2*)&OS[ra*132 + col] = make_float2(o[nt][0]*inva, o[nt][1]*inva);
        *(float2*)&OS[rb*132 + col] = make_float2(o[nt][2]*invb, o[nt][3]*invb);
    }
    __syncthreads();
    for (int i = tid; i < 128*32; i += 512) {
        int r = i >> 5, w4 = (i & 31) * 4;
        *(float4*)(out + ((size_t)(b*C_ + r0 + r)*H_ + h)*W_ + w4) = *(float4*)&OS[r*132 + w4];
    }
}

// ---------------------------------------------------------------------------
extern "C" void kernel_launch(void* const* d_in, const int* in_sizes, int n_in,
                              void* d_out, int out_size)
{
    (void)in_sizes; (void)n_in; (void)out_size;
    const float* hidden = (const float*)d_in[0];
    const float* ctx    = (const float*)d_in[1];
    const float* qdw = (const float*)d_in[2];
    const float* qdb = (const float*)d_in[3];
    const float* qpw = (const float*)d_in[4];
    const float* qpb = (const float*)d_in[5];
    const float* kdw = (const float*)d_in[6];
    const float* kdb = (const float*)d_in[7];
    const float* kpw = (const float*)d_in[8];
    const float* kpb = (const float*)d_in[9];
    const float* vdw = (const float*)d_in[10];
    const float* vdb = (const float*)d_in[11];
    const float* vpw = (const float*)d_in[12];
    const float* vpb = (const float*)d_in[13];
    float* out = (float*)d_out;

    __nv_bfloat16 *whi, *wlo;
    __nv_bfloat16 *t0h, *t0l, *t1h, *t1l, *t2h, *t2l;
    __nv_bfloat16 *qhi, *qlo, *khi, *klo, *vhi, *vlo;
    cudaGetSymbolAddress((void**)&whi, g_whi);
    cudaGetSymbolAddress((void**)&wlo, g_wlo);
    cudaGetSymbolAddress((void**)&t0h, g_t0h);
    cudaGetSymbolAddress((void**)&t0l, g_t0l);
    cudaGetSymbolAddress((void**)&t1h, g_t1h);
    cudaGetSymbolAddress((void**)&t1l, g_t1l);
    cudaGetSymbolAddress((void**)&t2h, g_t2h);
    cudaGetSymbolAddress((void**)&t2l, g_t2l);
    cudaGetSymbolAddress((void**)&qhi, g_qhi);
    cudaGetSymbolAddress((void**)&qlo, g_qlo);
    cudaGetSymbolAddress((void**)&khi, g_khi);
    cudaGetSymbolAddress((void**)&klo, g_klo);
    cudaGetSymbolAddress((void**)&vhi, g_vhi);
    cudaGetSymbolAddress((void**)&vlo, g_vlo);

    cudaFuncSetAttribute(pw_mma_kernel, cudaFuncAttributeMaxDynamicSharedMemorySize, PWS_SMEM);
    cudaFuncSetAttribute(attn_mma_kernel, cudaFuncAttributeMaxDynamicSharedMemorySize, ATT_SMEM);

    dim3 dsg(C_/32, H_, 3*B_);
    dim3 pwg(6, H_, B_);
    dim3 atg(2, H_, B_);

    wsplit_kernel<<<3*C_*C_/256, 256>>>(qpw, kpw, vpw, whi, wlo);
    dwsplit_kernel<<<dsg, 256>>>(hidden, ctx, qdw, qdb, kdw, kdb, vdw, vdb,
                                 t0h, t0l, t1h, t1l, t2h, t2l);
    pw_mma_kernel<<<pwg, 256, PWS_SMEM>>>(t0h, t0l, t1h, t1l, t2h, t2l,
                                          whi, wlo, qpb, kpb, vpb,
                                          qhi, qlo, khi, klo, vhi, vlo);
    attn_mma_kernel<<<atg, 512, ATT_SMEM>>>(qhi, qlo, khi, klo, vhi, vlo, out);
}

// round 13
// speedup vs baseline: 1.0209x; 1.0209x over previous
#include <cuda_runtime.h>
#include <cuda_bf16.h>
#include <cstdint>

#define B_ 8
#define C_ 256
#define H_ 128
#define W_ 128
#define NEL (B_*C_*H_*W_)

// Scratch (no allocation allowed -> __device__ globals)
__device__ __nv_bfloat16 g_whi[3 * C_ * C_];   // weight hi, K-major [o][c]
__device__ __nv_bfloat16 g_wlo[3 * C_ * C_];   // weight lo
__device__ __nv_bfloat16 g_t0h[NEL];           // dw-out hi/lo per chain, [b][h][w][c]
__device__ __nv_bfloat16 g_t0l[NEL];
__device__ __nv_bfloat16 g_t1h[NEL];
__device__ __nv_bfloat16 g_t1l[NEL];
__device__ __nv_bfloat16 g_t2h[NEL];
__device__ __nv_bfloat16 g_t2l[NEL];
__device__ __nv_bfloat16 g_qhi[NEL];           // q hi, [b][h][c][w]
__device__ __nv_bfloat16 g_qlo[NEL];
__device__ __nv_bfloat16 g_khi[NEL];           // k hi, [b][h][c][w]
__device__ __nv_bfloat16 g_klo[NEL];
__device__ __nv_bfloat16 g_vhi[NEL];           // v hi, [b][h][w][c]
__device__ __nv_bfloat16 g_vlo[NEL];

// ---- cp.async helpers ----
__device__ __forceinline__ uint32_t saddr(const void* p) {
    return (uint32_t)__cvta_generic_to_shared(p);
}
__device__ __forceinline__ void cp16(uint32_t dst, const void* src) {
    asm volatile("cp.async.cg.shared.global [%0], [%1], 16;" :: "r"(dst), "l"(src));
}
#define CP_COMMIT asm volatile("cp.async.commit_group;")
#define CP_WAIT0  asm volatile("cp.async.wait_group 0;")
#define CP_WAIT1  asm volatile("cp.async.wait_group 1;")

// ---- mma.sync / ldmatrix helpers (plain sm_103 features) ----
__device__ __forceinline__ void ldmx4(uint32_t* r, uint32_t addr) {
    asm volatile("ldmatrix.sync.aligned.m8n8.x4.shared.b16 {%0,%1,%2,%3}, [%4];"
                 : "=r"(r[0]), "=r"(r[1]), "=r"(r[2]), "=r"(r[3]) : "r"(addr));
}
__device__ __forceinline__ void mma16816(float* d, const uint32_t* a, const uint32_t* b) {
    asm volatile(
        "mma.sync.aligned.m16n8k16.row.col.f32.bf16.bf16.f32 "
        "{%0,%1,%2,%3}, {%4,%5,%6,%7}, {%8,%9}, {%0,%1,%2,%3};"
        : "+f"(d[0]), "+f"(d[1]), "+f"(d[2]), "+f"(d[3])
        : "r"(a[0]), "r"(a[1]), "r"(a[2]), "r"(a[3]), "r"(b[0]), "r"(b[1]));
}
__device__ __forceinline__ void split_bf16(float x, __nv_bfloat16& h, __nv_bfloat16& l) {
    h = __float2bfloat16_rn(x);
    l = __float2bfloat16_rn(x - __bfloat162float(h));
}

// ---------------------------------------------------------------------------
// Merged weight split: {q,k,v} pw weights fp32 -> hi/lo bf16. One launch.
// ---------------------------------------------------------------------------
__global__ void wsplit_kernel(const float* __restrict__ qpw,
                              const float* __restrict__ kpw,
                              const float* __restrict__ vpw,
                              __nv_bfloat16* __restrict__ hi,
                              __nv_bfloat16* __restrict__ lo)
{
    int i = blockIdx.x * 256 + threadIdx.x;
    int chain = i / (C_ * C_), j = i % (C_ * C_);
    const float* W = (chain == 0) ? qpw : (chain == 1) ? kpw : vpw;
    split_bf16(W[j], hi[i], lo[i]);
}

// ---------------------------------------------------------------------------
// MERGED fused depthwise 3x3 + bias + transpose + bf16 split (unchanged).
// ---------------------------------------------------------------------------
#define DSP 132
__global__ __launch_bounds__(256) void dwsplit_kernel(
    const float* __restrict__ hidden, const float* __restrict__ ctx,
    const float* __restrict__ qdw, const float* __restrict__ qdb,
    const float* __restrict__ kdw, const float* __restrict__ kdb,
    const float* __restrict__ vdw, const float* __restrict__ vdb,
    __nv_bfloat16* __restrict__ t0h, __nv_bfloat16* __restrict__ t0l,
    __nv_bfloat16* __restrict__ t1h, __nv_bfloat16* __restrict__ t1l,
    __nv_bfloat16* __restrict__ t2h, __nv_bfloat16* __restrict__ t2l)
{
    __shared__ float S[32 * DSP];
    const int c0 = blockIdx.x * 32;
    const int h = blockIdx.y;
    const int zz = blockIdx.z;
    const int chain = zz % 3, b = zz / 3;
    const float* x    = (chain == 0) ? hidden : ctx;
    const float* wgt  = (chain == 0) ? qdw : (chain == 1) ? kdw : vdw;
    const float* bias = (chain == 0) ? qdb : (chain == 1) ? kdb : vdb;
    __nv_bfloat16* hi = (chain == 0) ? t0h : (chain == 1) ? t1h : t2h;
    __nv_bfloat16* lo = (chain == 0) ? t0l : (chain == 1) ? t1l : t2l;

    const int tid = threadIdx.x;
    const int tx = tid & 31, ty = tid >> 5;
    const int w0 = tx * 4;

    #pragma unroll
    for (int j = 0; j < 4; j++) {
        const int cc = ty + j * 8;
        const int c = c0 + cc;
        const float* wc = wgt + c * 9;
        const float* plane = x + (b * C_ + c) * (H_ * W_);
        float bv = __ldg(&bias[c]);
        float4 acc = make_float4(bv, bv, bv, bv);
        #pragma unroll
        for (int i = 0; i < 3; i++) {
            int hh = h + i - 1;
            if (hh < 0 || hh >= H_) continue;
            float4 xc = __ldg((const float4*)(plane + hh * W_ + w0));
            float xl = __shfl_up_sync(0xffffffffu, xc.w, 1);
            float xr = __shfl_down_sync(0xffffffffu, xc.x, 1);
            if (tx == 0)  xl = 0.f;
            if (tx == 31) xr = 0.f;
            float wl = __ldg(&wc[i*3+0]), wm = __ldg(&wc[i*3+1]), wr = __ldg(&wc[i*3+2]);
            acc.x += wl*xl   + wm*xc.x + wr*xc.y;
            acc.y += wl*xc.x + wm*xc.y + wr*xc.z;
            acc.z += wl*xc.y + wm*xc.z + wr*xc.w;
            acc.w += wl*xc.z + wm*xc.w + wr*xr;
        }
        *(float4*)&S[cc * DSP + w0] = acc;
    }
    __syncthreads();

    const int w = tid & 127;
    const int cb = (tid >> 7) * 16;
    __nv_bfloat16 hb[16], lb[16];
    #pragma unroll
    for (int e = 0; e < 16; e++)
        split_bf16(S[(cb + e) * DSP + w], hb[e], lb[e]);
    size_t idx = ((size_t)(b * H_ + h) * W_ + w) * C_ + c0 + cb;
    *(uint4*)(hi + idx)     = *(uint4*)&hb[0];
    *(uint4*)(hi + idx + 8) = *(uint4*)&hb[8];
    *(uint4*)(lo + idx)     = *(uint4*)&lb[0];
    *(uint4*)(lo + idx + 8) = *(uint4*)&lb[8];
}

// ---------------------------------------------------------------------------
// MERGED pointwise 1x1 split-bf16 mma.sync GEMM (unchanged).
// ---------------------------------------------------------------------------
#define MP2 72
#define PWT (128*MP2)
#define PW_STG (4*PWT)
#define PWS_SMEM (2*PW_STG*2)

__global__ __launch_bounds__(256, 1) void pw_mma_kernel(
    const __nv_bfloat16* __restrict__ t0h, const __nv_bfloat16* __restrict__ t0l,
    const __nv_bfloat16* __restrict__ t1h, const __nv_bfloat16* __restrict__ t1l,
    const __nv_bfloat16* __restrict__ t2h, const __nv_bfloat16* __restrict__ t2l,
    const __nv_bfloat16* __restrict__ whi_b, const __nv_bfloat16* __restrict__ wlo_b,
    const float* __restrict__ qpb, const float* __restrict__ kpb, const float* __restrict__ vpb,
    __nv_bfloat16* __restrict__ q_hi, __nv_bfloat16* __restrict__ q_lo,
    __nv_bfloat16* __restrict__ k_hi, __nv_bfloat16* __restrict__ k_lo,
    __nv_bfloat16* __restrict__ v_hi, __nv_bfloat16* __restrict__ v_lo)
{
    extern __shared__ char psm[];
    const uint32_t sbase = saddr(psm);
    const int chain = blockIdx.x >> 1;
    const int o0 = (blockIdx.x & 1) * 128;
    const int h = blockIdx.y, b = blockIdx.z;
    const int bh = b * H_ + h;
    const int tid = threadIdx.x;
    const int wid = tid >> 5, lane = tid & 31;
    const int m0 = (wid >> 2) * 64;
    const int n0 = (wid & 3) * 32;

    const __nv_bfloat16* thi = (chain == 0) ? t0h : (chain == 1) ? t1h : t2h;
    const __nv_bfloat16* tlo = (chain == 0) ? t0l : (chain == 1) ? t1l : t2l;
    const __nv_bfloat16* whi = whi_b + (size_t)chain * (C_ * C_);
    const __nv_bfloat16* wlo = wlo_b + (size_t)chain * (C_ * C_);
    const float* bias = (chain == 0) ? qpb : (chain == 1) ? kpb : vpb;
    __nv_bfloat16* ohi = (chain == 0) ? q_hi : (chain == 1) ? k_hi : v_hi;
    __nv_bfloat16* olo = (chain == 0) ? q_lo : (chain == 1) ? k_lo : v_lo;

    float d[4][4][4];
    #pragma unroll
    for (int mi = 0; mi < 4; mi++)
        #pragma unroll
        for (int ni = 0; ni < 4; ni++)
            { d[mi][ni][0]=0.f; d[mi][ni][1]=0.f; d[mi][ni][2]=0.f; d[mi][ni][3]=0.f; }

    int a_off[4], b_off[2];
    #pragma unroll
    for (int mi = 0; mi < 4; mi++)
        a_off[mi] = (m0 + mi*16 + (lane & 15)) * MP2 + (lane >> 4) * 8;
    #pragma unroll
    for (int p = 0; p < 2; p++) {
        int tl = lane >> 3;
        b_off[p] = (n0 + p*16 + (tl >> 1)*8 + (lane & 7)) * MP2 + (tl & 1) * 8;
    }

    const __nv_bfloat16* tbh = thi + (size_t)bh * (W_ * C_);
    const __nv_bfloat16* tbl = tlo + (size_t)bh * (W_ * C_);
    const int rl = tid >> 3, c8 = (tid & 7) * 8;

    #define PW_STAGE_LOAD(ch, sbuf) do { \
        const int kk_ = (ch) * 64; \
        uint32_t base_ = sbase + (uint32_t)(sbuf) * (PW_STG * 2); \
        _Pragma("unroll") \
        for (int rr = 0; rr < 4; rr++) { \
            int r = rl + rr * 32; \
            uint32_t doff = (uint32_t)(r * MP2 + c8) * 2; \
            cp16(base_ + 0*PWT*2 + doff, whi + (o0 + r) * C_ + kk_ + c8); \
            cp16(base_ + 1*PWT*2 + doff, wlo + (o0 + r) * C_ + kk_ + c8); \
            cp16(base_ + 2*PWT*2 + doff, tbh + r * C_ + kk_ + c8); \
            cp16(base_ + 3*PWT*2 + doff, tbl + r * C_ + kk_ + c8); \
        } } while (0)

    PW_STAGE_LOAD(0, 0); CP_COMMIT;

    for (int ch = 0; ch < 4; ch++) {
        if (ch < 3) { PW_STAGE_LOAD(ch + 1, (ch + 1) & 1); CP_COMMIT; CP_WAIT1; }
        else        { CP_WAIT0; }
        __syncthreads();
        const uint32_t sb0 = sbase + (uint32_t)(ch & 1) * (PW_STG * 2);

        #pragma unroll
        for (int ks = 0; ks < 4; ks++) {
            const int k0 = ks * 16;
            uint32_t ah[4][4], al[4][4], bh2[2][4], bl2[2][4];
            #pragma unroll
            for (int mi = 0; mi < 4; mi++) {
                ldmx4(ah[mi], sb0 + (a_off[mi] + k0) * 2);
                ldmx4(al[mi], sb0 + (PWT + a_off[mi] + k0) * 2);
            }
            #pragma unroll
            for (int p = 0; p < 2; p++) {
                ldmx4(bh2[p], sb0 + (2*PWT + b_off[p] + k0) * 2);
                ldmx4(bl2[p], sb0 + (3*PWT + b_off[p] + k0) * 2);
            }
            #pragma unroll
            for (int mi = 0; mi < 4; mi++)
                #pragma unroll
                for (int ni = 0; ni < 4; ni++)
                    mma16816(d[mi][ni], ah[mi], &bh2[ni >> 1][(ni & 1) * 2]);
            #pragma unroll
            for (int mi = 0; mi < 4; mi++)
                #pragma unroll
                for (int ni = 0; ni < 4; ni++)
                    mma16816(d[mi][ni], ah[mi], &bl2[ni >> 1][(ni & 1) * 2]);
            #pragma unroll
            for (int mi = 0; mi < 4; mi++)
                #pragma unroll
                for (int ni = 0; ni < 4; ni++)
                    mma16816(d[mi][ni], al[mi], &bh2[ni >> 1][(ni & 1) * 2]);
        }
        __syncthreads();
    }
    #undef PW_STAGE_LOAD

    if (chain != 2) {
        #pragma unroll
        for (int mi = 0; mi < 4; mi++) {
            int o1 = o0 + m0 + mi*16 + (lane >> 2);
            float bv1 = __ldg(&bias[o1]);
            float bv2 = __ldg(&bias[o1 + 8]);
            size_t r1 = ((size_t)bh * C_ + o1) * W_;
            size_t r2 = r1 + 8 * W_;
            #pragma unroll
            for (int ni = 0; ni < 4; ni++) {
                int wc = n0 + ni*8 + (lane & 3)*2;
                __nv_bfloat162 hp, lp;
                split_bf16(d[mi][ni][0] + bv1, hp.x, lp.x);
                split_bf16(d[mi][ni][1] + bv1, hp.y, lp.y);
                *(__nv_bfloat162*)(ohi + r1 + wc) = hp;
                *(__nv_bfloat162*)(olo + r1 + wc) = lp;
                split_bf16(d[mi][ni][2] + bv2, hp.x, lp.x);
                split_bf16(d[mi][ni][3] + bv2, hp.y, lp.y);
                *(__nv_bfloat162*)(ohi + r2 + wc) = hp;
                *(__nv_bfloat162*)(olo + r2 + wc) = lp;
            }
        }
    } else {
        __syncthreads();
        float* DS = (float*)psm;
        #pragma unroll
        for (int mi = 0; mi < 4; mi++) {
            int m_ = m0 + mi*16 + (lane >> 2);
            #pragma unroll
            for (int ni = 0; ni < 4; ni++) {
                int n_ = n0 + ni*8 + (lane & 3)*2;
                DS[n_*132 + m_]         = d[mi][ni][0];
                DS[(n_+1)*132 + m_]     = d[mi][ni][1];
                DS[n_*132 + m_ + 8]     = d[mi][ni][2];
                DS[(n_+1)*132 + m_ + 8] = d[mi][ni][3];
            }
        }
        __syncthreads();
        for (int i = tid; i < 128*32; i += 256) {
            int w = i >> 5, o4 = (i & 31) * 4;
            float4 v = *(float4*)&DS[w*132 + o4];
            float4 bv = *(const float4*)&bias[o0 + o4];
            size_t idx = ((size_t)bh * W_ + w) * C_ + o0 + o4;
            __nv_bfloat162 h01, h23, l01, l23;
            split_bf16(v.x + bv.x, h01.x, l01.x);
            split_bf16(v.y + bv.y, h01.y, l01.y);
            split_bf16(v.z + bv.z, h23.x, l23.x);
            split_bf16(v.w + bv.w, h23.y, l23.y);
            *(__nv_bfloat162*)(ohi + idx)     = h01;
            *(__nv_bfloat162*)(ohi + idx + 2) = h23;
            *(__nv_bfloat162*)(olo + idx)     = l01;
            *(__nv_bfloat162*)(olo + idx + 2) = l23;
        }
    }
}

// ---------------------------------------------------------------------------
// Attention, 2 CTAs/SM: 64-row Q tiles, K/V in 64-row pieces through one
// buffer.  256 threads, warp grid 4(m) x 2(n-half32): warp = 16 rows x 32
// cols per piece.  smem ~105.5 KB -> two CTAs interleave their phases so
// one CTA's MMA hides the other's loads/softmax.
// ---------------------------------------------------------------------------
#define ATR 64
#define AMP 136
#define AQHI 0
#define AQLO (ATR*AMP)
#define AKVHI (2*ATR*AMP)
#define AKVLO (3*ATR*AMP)
#define APHI (4*ATR*AMP)
#define APLO (5*ATR*AMP)
#define APMX (6*ATR*AMP)
#define ATT_SMEM (6*ATR*AMP*2 + 1088)

__global__ __launch_bounds__(256, 2) void attn_mma_kernel(
    const __nv_bfloat16* __restrict__ qhi, const __nv_bfloat16* __restrict__ qlo,
    const __nv_bfloat16* __restrict__ khi, const __nv_bfloat16* __restrict__ klo,
    const __nv_bfloat16* __restrict__ vhi, const __nv_bfloat16* __restrict__ vlo,
    float* __restrict__ out)
{
    extern __shared__ char smraw[];
    const uint32_t sb = saddr(smraw);
    float* pm = (float*)(smraw + (size_t)APMX * 2);   // [2][64] partial max
    float* ps = pm + 128;                              // [2][64] partial sum
    const int r0 = blockIdx.x * ATR;
    const int h = blockIdx.y, b = blockIdx.z;
    const int bh = b * H_ + h;
    const size_t bho = (size_t)bh * (C_ * W_);
    const int tid = threadIdx.x;
    const int wid = tid >> 5, lane = tid & 31;
    const int m0 = (wid >> 1) * 16;      // warp row tile (0/16/32/48)
    const int nh = wid & 1;              // warp 32-col half within a piece
    const float scale = 0.17677669529663687f;

    const int a_off = (m0 + (lane & 15)) * AMP + (lane >> 4) * 8;
    int b_off[2];
    {
        int tl = lane >> 3;
        #pragma unroll
        for (int p = 0; p < 2; p++)
            b_off[p] = (nh*32 + p*16 + (tl >> 1)*8 + (lane & 7)) * AMP + (tl & 1) * 8;
    }
    const int ra = m0 + (lane >> 2);     // 0..55
    const int rb = ra + 8;               // 8..63
    const int pcol0 = (lane & 3) * 2;

    const int rl = tid >> 4, c8 = (tid & 15) * 8;    // 16 rows/pass, 4 passes
    #define ALOAD(dstbase, src, rlen, roff, coff) do { \
        _Pragma("unroll") \
        for (int j = 0; j < 4; j++) { \
            int r = rl + j * 16; \
            cp16(sb + ((dstbase) + r * AMP + c8) * 2, \
                 (src) + ((size_t)((roff) + r)) * (rlen) + (coff) + c8); \
        } } while (0)

    // GEMM piece macro: acc[piece*4 .. +3][4] += A(frag base abase) * Bpiece
    #define GEMM_PIECE(acc, abase, p) do { \
        float* s4 = &acc[(p)*4][0]; \
        _Pragma("unroll") \
        for (int kw = 0; kw < 8; kw++) { \
            uint32_t fh[4], fl[4]; \
            ldmx4(fh, sb + ((abase) + a_off + kw*16) * 2); \
            ldmx4(fl, sb + ((abase) + ATR*AMP + a_off + kw*16) * 2); \
            uint32_t bh0[4], bh1[4], bl0[4], bl1[4]; \
            ldmx4(bh0, sb + (AKVHI + b_off[0] + kw*16) * 2); \
            ldmx4(bh1, sb + (AKVHI + b_off[1] + kw*16) * 2); \
            ldmx4(bl0, sb + (AKVLO + b_off[0] + kw*16) * 2); \
            ldmx4(bl1, sb + (AKVLO + b_off[1] + kw*16) * 2); \
            mma16816(s4+0,  fh, &bh0[0]); mma16816(s4+4,  fh, &bh0[2]); \
            mma16816(s4+8,  fh, &bh1[0]); mma16816(s4+12, fh, &bh1[2]); \
            mma16816(s4+0,  fh, &bl0[0]); mma16816(s4+4,  fh, &bl0[2]); \
            mma16816(s4+8,  fh, &bl1[0]); mma16816(s4+12, fh, &bl1[2]); \
            mma16816(s4+0,  fl, &bh0[0]); mma16816(s4+4,  fl, &bh0[2]); \
            mma16816(s4+8,  fl, &bh1[0]); mma16816(s4+12, fl, &bh1[2]); \
        } } while (0)

    float o[8][4];
    #pragma unroll
    for (int nt = 0; nt < 8; nt++) { o[nt][0]=0.f; o[nt][1]=0.f; o[nt][2]=0.f; o[nt][3]=0.f; }
    float m_a = -1e30f, m_b = -1e30f, l_a = 0.f, l_b = 0.f;

    // Q (persistent, 64 rows) + K dt0 piece0
    ALOAD(AQHI,  qhi + bho, W_, r0, 0);
    ALOAD(AQLO,  qlo + bho, W_, r0, 0);
    ALOAD(AKVHI, khi + bho, W_, 0, 0);
    ALOAD(AKVLO, klo + bho, W_, 0, 0);
    CP_COMMIT; CP_WAIT0; __syncthreads();

    for (int dt = 0; dt < 2; dt++) {
        // ---- S = Q K^T chunk, two 64-d-row pieces ----
        float s[8][4];
        #pragma unroll
        for (int nt = 0; nt < 8; nt++) { s[nt][0]=0.f; s[nt][1]=0.f; s[nt][2]=0.f; s[nt][3]=0.f; }

        GEMM_PIECE(s, AQHI, 0);
        __syncthreads();
        ALOAD(AKVHI, khi + bho, W_, dt*128 + 64, 0);
        ALOAD(AKVLO, klo + bho, W_, dt*128 + 64, 0);
        CP_COMMIT; CP_WAIT0; __syncthreads();
        GEMM_PIECE(s, AQHI, 1);
        __syncthreads();
        // prefetch V piece0 (w rows 0..63) — overlaps softmax
        ALOAD(AKVHI, vhi + bho, C_, 0, dt*128);
        ALOAD(AKVLO, vlo + bho, C_, 0, dt*128);
        CP_COMMIT;

        // ---- online softmax, cross-warp-pair combine ----
        #pragma unroll
        for (int nt = 0; nt < 8; nt++) {
            s[nt][0] *= scale; s[nt][1] *= scale; s[nt][2] *= scale; s[nt][3] *= scale;
        }
        float mc_a = -1e30f, mc_b = -1e30f;
        #pragma unroll
        for (int nt = 0; nt < 8; nt++) {
            mc_a = fmaxf(mc_a, fmaxf(s[nt][0], s[nt][1]));
            mc_b = fmaxf(mc_b, fmaxf(s[nt][2], s[nt][3]));
        }
        mc_a = fmaxf(mc_a, __shfl_xor_sync(0xffffffffu, mc_a, 1));
        mc_a = fmaxf(mc_a, __shfl_xor_sync(0xffffffffu, mc_a, 2));
        mc_b = fmaxf(mc_b, __shfl_xor_sync(0xffffffffu, mc_b, 1));
        mc_b = fmaxf(mc_b, __shfl_xor_sync(0xffffffffu, mc_b, 2));
        if ((lane & 3) == 0) { pm[nh*64 + ra] = mc_a; pm[nh*64 + rb] = mc_b; }
        __syncthreads();
        float m_na = fmaxf(m_a, fmaxf(mc_a, pm[(nh^1)*64 + ra]));
        float m_nb = fmaxf(m_b, fmaxf(mc_b, pm[(nh^1)*64 + rb]));
        float ca = __expf(m_a - m_na), cb = __expf(m_b - m_nb);
        float la_c = 0.f, lb_c = 0.f;
        #pragma unroll
        for (int nt = 0; nt < 8; nt++) {
            float e0 = __expf(s[nt][0] - m_na), e1 = __expf(s[nt][1] - m_na);
            float e2 = __expf(s[nt][2] - m_nb), e3 = __expf(s[nt][3] - m_nb);
            la_c += e0 + e1; lb_c += e2 + e3;
            int col = (nt >> 2)*64 + nh*32 + (nt & 3)*8 + pcol0;
            __nv_bfloat162 hp, lp;
            split_bf16(e0, hp.x, lp.x); split_bf16(e1, hp.y, lp.y);
            *(__nv_bfloat162*)(smraw + (APHI + ra*AMP + col)*2) = hp;
            *(__nv_bfloat162*)(smraw + (APLO + ra*AMP + col)*2) = lp;
            split_bf16(e2, hp.x, lp.x); split_bf16(e3, hp.y, lp.y);
            *(__nv_bfloat162*)(smraw + (APHI + rb*AMP + col)*2) = hp;
            *(__nv_bfloat162*)(smraw + (APLO + rb*AMP + col)*2) = lp;
            o[nt][0] *= ca; o[nt][1] *= ca; o[nt][2] *= cb; o[nt][3] *= cb;
        }
        la_c += __shfl_xor_sync(0xffffffffu, la_c, 1);
        la_c += __shfl_xor_sync(0xffffffffu, la_c, 2);
        lb_c += __shfl_xor_sync(0xffffffffu, lb_c, 1);
        lb_c += __shfl_xor_sync(0xffffffffu, lb_c, 2);
        if ((lane & 3) == 0) { ps[nh*64 + ra] = la_c; ps[nh*64 + rb] = lb_c; }
        __syncthreads();
        l_a = l_a * ca + la_c + ps[(nh^1)*64 + ra];
        l_b = l_b * cb + lb_c + ps[(nh^1)*64 + rb];
        m_a = m_na;  m_b = m_nb;
        CP_WAIT0; __syncthreads();            // V piece0 ready; P visible

        // ---- O += P V chunk, two 64-w-row pieces ----
        GEMM_PIECE(o, APHI, 0);
        __syncthreads();
        ALOAD(AKVHI, vhi + bho, C_, 64, dt*128);
        ALOAD(AKVLO, vlo + bho, C_, 64, dt*128);
        CP_COMMIT; CP_WAIT0; __syncthreads();
        GEMM_PIECE(o, APHI, 1);

        if (dt == 0) {
            __syncthreads();                  // V consumed; load K dt1 piece0
            ALOAD(AKVHI, khi + bho, W_, 128, 0);
            ALOAD(AKVLO, klo + bho, W_, 128, 0);
            CP_COMMIT; CP_WAIT0; __syncthreads();
        }
    }
    #undef ALOAD
    #undef GEMM_PIECE

    // ---- epilogue ----
    float inva = 1.f / l_a, invb = 1.f / l_b;
    __syncthreads();                          // all PV reads of P done
    float* OS = (float*)(smraw + (size_t)APHI * 2);
    #pragma unroll
    for (int nt = 0; nt < 8; nt++) {
        int col = (nt >> 2)*64 + nh*32 + (nt & 3)*8 + pcol0;
        *(float2*)&OS[ra*132 + col] = make_float2(o[nt][0]*inva, o[nt][1]*inva);
        *(float2*)&OS[rb*132 + col] = make_float2(o[nt][2]*invb, o[nt][3]*invb);
    }
    __syncthreads();
    for (int i = tid; i < ATR*32; i += 256) {
        int r = i >> 5, w4 = (i & 31) * 4;
        *(float4*)(out + ((size_t)(b*C_ + r0 + r)*H_ + h)*W_ + w4) = *(float4*)&OS[r*132 + w4];
    }
}

// ---------------------------------------------------------------------------
extern "C" void kernel_launch(void* const* d_in, const int* in_sizes, int n_in,
                              void* d_out, int out_size)
{
    (void)in_sizes; (void)n_in; (void)out_size;
    const float* hidden = (const float*)d_in[0];
    const float* ctx    = (const float*)d_in[1];
    const float* qdw = (const float*)d_in[2];
    const float* qdb = (const float*)d_in[3];
    const float* qpw = (const float*)d_in[4];
    const float* qpb = (const float*)d_in[5];
    const float* kdw = (const float*)d_in[6];
    const float* kdb = (const float*)d_in[7];
    const float* kpw = (const float*)d_in[8];
    const float* kpb = (const float*)d_in[9];
    const float* vdw = (const float*)d_in[10];
    const float* vdb = (const float*)d_in[11];
    const float* vpw = (const float*)d_in[12];
    const float* vpb = (const float*)d_in[13];
    float* out = (float*)d_out;

    __nv_bfloat16 *whi, *wlo;
    __nv_bfloat16 *t0h, *t0l, *t1h, *t1l, *t2h, *t2l;
    __nv_bfloat16 *qhi, *qlo, *khi, *klo, *vhi, *vlo;
    cudaGetSymbolAddress((void**)&whi, g_whi);
    cudaGetSymbolAddress((void**)&wlo, g_wlo);
    cudaGetSymbolAddress((void**)&t0h, g_t0h);
    cudaGetSymbolAddress((void**)&t0l, g_t0l);
    cudaGetSymbolAddress((void**)&t1h, g_t1h);
    cudaGetSymbolAddress((void**)&t1l, g_t1l);
    cudaGetSymbolAddress((void**)&t2h, g_t2h);
    cudaGetSymbolAddress((void**)&t2l, g_t2l);
    cudaGetSymbolAddress((void**)&qhi, g_qhi);
    cudaGetSymbolAddress((void**)&qlo, g_qlo);
    cudaGetSymbolAddress((void**)&khi, g_khi);
    cudaGetSymbolAddress((void**)&klo, g_klo);
    cudaGetSymbolAddress((void**)&vhi, g_vhi);
    cudaGetSymbolAddress((void**)&vlo, g_vlo);

    cudaFuncSetAttribute(pw_mma_kernel, cudaFuncAttributeMaxDynamicSharedMemorySize, PWS_SMEM);
    cudaFuncSetAttribute(attn_mma_kernel, cudaFuncAttributeMaxDynamicSharedMemorySize, ATT_SMEM);

    dim3 dsg(C_/32, H_, 3*B_);
    dim3 pwg(6, H_, B_);
    dim3 atg(4, H_, B_);

    wsplit_kernel<<<3*C_*C_/256, 256>>>(qpw, kpw, vpw, whi, wlo);
    dwsplit_kernel<<<dsg, 256>>>(hidden, ctx, qdw, qdb, kdw, kdb, vdw, vdb,
                                 t0h, t0l, t1h, t1l, t2h, t2l);
    pw_mma_kernel<<<pwg, 256, PWS_SMEM>>>(t0h, t0l, t1h, t1l, t2h, t2l,
                                          whi, wlo, qpb, kpb, vpb,
                                          qhi, qlo, khi, klo, vhi, vlo);
    attn_mma_kernel<<<atg, 256, ATT_SMEM>>>(qhi, qlo, khi, klo, vhi, vlo, out);
}

// round 16
// speedup vs baseline: 1.0609x; 1.0392x over previous
#include <cuda_runtime.h>
#include <cuda_bf16.h>
#include <cstdint>

#define B_ 8
#define C_ 256
#define H_ 128
#define W_ 128
#define NEL (B_*C_*H_*W_)

// Scratch (no allocation allowed -> __device__ globals)
__device__ __nv_bfloat16 g_whi[3 * C_ * C_];   // weight hi, K-major [o][c]
__device__ __nv_bfloat16 g_wlo[3 * C_ * C_];   // weight lo
__device__ __nv_bfloat16 g_t0h[NEL];           // dw-out hi/lo per chain, [b][h][w][c]
__device__ __nv_bfloat16 g_t0l[NEL];
__device__ __nv_bfloat16 g_t1h[NEL];
__device__ __nv_bfloat16 g_t1l[NEL];
__device__ __nv_bfloat16 g_t2h[NEL];
__device__ __nv_bfloat16 g_t2l[NEL];
__device__ __nv_bfloat16 g_qhi[NEL];           // q hi, [b][h][c][w]
__device__ __nv_bfloat16 g_qlo[NEL];
__device__ __nv_bfloat16 g_khi[NEL];           // k hi, [b][h][c][w]
__device__ __nv_bfloat16 g_klo[NEL];
__device__ __nv_bfloat16 g_vhi[NEL];           // v hi, [b][h][w][c]
__device__ __nv_bfloat16 g_vlo[NEL];

// ---- cp.async helpers ----
__device__ __forceinline__ uint32_t saddr(const void* p) {
    return (uint32_t)__cvta_generic_to_shared(p);
}
__device__ __forceinline__ void cp16(uint32_t dst, const void* src) {
    asm volatile("cp.async.cg.shared.global [%0], [%1], 16;" :: "r"(dst), "l"(src));
}
#define CP_COMMIT asm volatile("cp.async.commit_group;")
#define CP_WAIT0  asm volatile("cp.async.wait_group 0;")
#define CP_WAIT1  asm volatile("cp.async.wait_group 1;")

// ---- mma.sync / ldmatrix helpers (plain sm_103 features) ----
__device__ __forceinline__ void ldmx4(uint32_t* r, uint32_t addr) {
    asm volatile("ldmatrix.sync.aligned.m8n8.x4.shared.b16 {%0,%1,%2,%3}, [%4];"
                 : "=r"(r[0]), "=r"(r[1]), "=r"(r[2]), "=r"(r[3]) : "r"(addr));
}
__device__ __forceinline__ void mma16816(float* d, const uint32_t* a, const uint32_t* b) {
    asm volatile(
        "mma.sync.aligned.m16n8k16.row.col.f32.bf16.bf16.f32 "
        "{%0,%1,%2,%3}, {%4,%5,%6,%7}, {%8,%9}, {%0,%1,%2,%3};"
        : "+f"(d[0]), "+f"(d[1]), "+f"(d[2]), "+f"(d[3])
        : "r"(a[0]), "r"(a[1]), "r"(a[2]), "r"(a[3]), "r"(b[0]), "r"(b[1]));
}
__device__ __forceinline__ void split_bf16(float x, __nv_bfloat16& h, __nv_bfloat16& l) {
    h = __float2bfloat16_rn(x);
    l = __float2bfloat16_rn(x - __bfloat162float(h));
}

// ---------------------------------------------------------------------------
// Merged weight split: {q,k,v} pw weights fp32 -> hi/lo bf16. One launch.
// ---------------------------------------------------------------------------
__global__ void wsplit_kernel(const float* __restrict__ qpw,
                              const float* __restrict__ kpw,
                              const float* __restrict__ vpw,
                              __nv_bfloat16* __restrict__ hi,
                              __nv_bfloat16* __restrict__ lo)
{
    int i = blockIdx.x * 256 + threadIdx.x;
    int chain = i / (C_ * C_), j = i % (C_ * C_);
    const float* W = (chain == 0) ? qpw : (chain == 1) ? kpw : vpw;
    split_bf16(W[j], hi[i], lo[i]);
}

// ---------------------------------------------------------------------------
// MERGED fused depthwise 3x3 + bias + transpose + bf16 split (unchanged).
// ---------------------------------------------------------------------------
#define DSP 132
__global__ __launch_bounds__(256) void dwsplit_kernel(
    const float* __restrict__ hidden, const float* __restrict__ ctx,
    const float* __restrict__ qdw, const float* __restrict__ qdb,
    const float* __restrict__ kdw, const float* __restrict__ kdb,
    const float* __restrict__ vdw, const float* __restrict__ vdb,
    __nv_bfloat16* __restrict__ t0h, __nv_bfloat16* __restrict__ t0l,
    __nv_bfloat16* __restrict__ t1h, __nv_bfloat16* __restrict__ t1l,
    __nv_bfloat16* __restrict__ t2h, __nv_bfloat16* __restrict__ t2l)
{
    __shared__ float S[32 * DSP];
    const int c0 = blockIdx.x * 32;
    const int h = blockIdx.y;
    const int zz = blockIdx.z;
    const int chain = zz % 3, b = zz / 3;
    const float* x    = (chain == 0) ? hidden : ctx;
    const float* wgt  = (chain == 0) ? qdw : (chain == 1) ? kdw : vdw;
    const float* bias = (chain == 0) ? qdb : (chain == 1) ? kdb : vdb;
    __nv_bfloat16* hi = (chain == 0) ? t0h : (chain == 1) ? t1h : t2h;
    __nv_bfloat16* lo = (chain == 0) ? t0l : (chain == 1) ? t1l : t2l;

    const int tid = threadIdx.x;
    const int tx = tid & 31, ty = tid >> 5;
    const int w0 = tx * 4;

    #pragma unroll
    for (int j = 0; j < 4; j++) {
        const int cc = ty + j * 8;
        const int c = c0 + cc;
        const float* wc = wgt + c * 9;
        const float* plane = x + (b * C_ + c) * (H_ * W_);
        float bv = __ldg(&bias[c]);
        float4 acc = make_float4(bv, bv, bv, bv);
        #pragma unroll
        for (int i = 0; i < 3; i++) {
            int hh = h + i - 1;
            if (hh < 0 || hh >= H_) continue;
            float4 xc = __ldg((const float4*)(plane + hh * W_ + w0));
            float xl = __shfl_up_sync(0xffffffffu, xc.w, 1);
            float xr = __shfl_down_sync(0xffffffffu, xc.x, 1);
            if (tx == 0)  xl = 0.f;
            if (tx == 31) xr = 0.f;
            float wl = __ldg(&wc[i*3+0]), wm = __ldg(&wc[i*3+1]), wr = __ldg(&wc[i*3+2]);
            acc.x += wl*xl   + wm*xc.x + wr*xc.y;
            acc.y += wl*xc.x + wm*xc.y + wr*xc.z;
            acc.z += wl*xc.y + wm*xc.z + wr*xc.w;
            acc.w += wl*xc.z + wm*xc.w + wr*xr;
        }
        *(float4*)&S[cc * DSP + w0] = acc;
    }
    __syncthreads();

    const int w = tid & 127;
    const int cb = (tid >> 7) * 16;
    __nv_bfloat16 hb[16], lb[16];
    #pragma unroll
    for (int e = 0; e < 16; e++)
        split_bf16(S[(cb + e) * DSP + w], hb[e], lb[e]);
    size_t idx = ((size_t)(b * H_ + h) * W_ + w) * C_ + c0 + cb;
    *(uint4*)(hi + idx)     = *(uint4*)&hb[0];
    *(uint4*)(hi + idx + 8) = *(uint4*)&hb[8];
    *(uint4*)(lo + idx)     = *(uint4*)&lb[0];
    *(uint4*)(lo + idx + 8) = *(uint4*)&lb[8];
}

// ---------------------------------------------------------------------------
// MERGED pointwise 1x1 split-bf16 mma.sync GEMM — now 2 CTAs/SM.
// 32-wide K chunks (8 chunks, double-buffered): smem 80KB/CTA.
// grid (6, H, B): chain = x>>1, o-tile = x&1.
// ---------------------------------------------------------------------------
#define MP3 40
#define PWT3 (128*MP3)          // elems per tile (128 rows x 32 cols, pitch 40)
#define PW_STG3 (4*PWT3)        // elems per stage (AHI,ALO,BHI,BLO)
#define PWS_SMEM (2*PW_STG3*2)  // 81920 bytes -> 2 CTAs/SM

__global__ __launch_bounds__(256, 2) void pw_mma_kernel(
    const __nv_bfloat16* __restrict__ t0h, const __nv_bfloat16* __restrict__ t0l,
    const __nv_bfloat16* __restrict__ t1h, const __nv_bfloat16* __restrict__ t1l,
    const __nv_bfloat16* __restrict__ t2h, const __nv_bfloat16* __restrict__ t2l,
    const __nv_bfloat16* __restrict__ whi_b, const __nv_bfloat16* __restrict__ wlo_b,
    const float* __restrict__ qpb, const float* __restrict__ kpb, const float* __restrict__ vpb,
    __nv_bfloat16* __restrict__ q_hi, __nv_bfloat16* __restrict__ q_lo,
    __nv_bfloat16* __restrict__ k_hi, __nv_bfloat16* __restrict__ k_lo,
    __nv_bfloat16* __restrict__ v_hi, __nv_bfloat16* __restrict__ v_lo)
{
    extern __shared__ char psm[];
    const uint32_t sbase = saddr(psm);
    const int chain = blockIdx.x >> 1;
    const int o0 = (blockIdx.x & 1) * 128;
    const int h = blockIdx.y, b = blockIdx.z;
    const int bh = b * H_ + h;
    const int tid = threadIdx.x;
    const int wid = tid >> 5, lane = tid & 31;
    const int m0 = (wid >> 2) * 64;
    const int n0 = (wid & 3) * 32;

    const __nv_bfloat16* thi = (chain == 0) ? t0h : (chain == 1) ? t1h : t2h;
    const __nv_bfloat16* tlo = (chain == 0) ? t0l : (chain == 1) ? t1l : t2l;
    const __nv_bfloat16* whi = whi_b + (size_t)chain * (C_ * C_);
    const __nv_bfloat16* wlo = wlo_b + (size_t)chain * (C_ * C_);
    const float* bias = (chain == 0) ? qpb : (chain == 1) ? kpb : vpb;
    __nv_bfloat16* ohi = (chain == 0) ? q_hi : (chain == 1) ? k_hi : v_hi;
    __nv_bfloat16* olo = (chain == 0) ? q_lo : (chain == 1) ? k_lo : v_lo;

    float d[4][4][4];
    #pragma unroll
    for (int mi = 0; mi < 4; mi++)
        #pragma unroll
        for (int ni = 0; ni < 4; ni++)
            { d[mi][ni][0]=0.f; d[mi][ni][1]=0.f; d[mi][ni][2]=0.f; d[mi][ni][3]=0.f; }

    int a_off[4], b_off[2];
    #pragma unroll
    for (int mi = 0; mi < 4; mi++)
        a_off[mi] = (m0 + mi*16 + (lane & 15)) * MP3 + (lane >> 4) * 8;
    #pragma unroll
    for (int p = 0; p < 2; p++) {
        int tl = lane >> 3;
        b_off[p] = (n0 + p*16 + (tl >> 1)*8 + (lane & 7)) * MP3 + (tl & 1) * 8;
    }

    const __nv_bfloat16* tbh = thi + (size_t)bh * (W_ * C_);
    const __nv_bfloat16* tbl = tlo + (size_t)bh * (W_ * C_);
    const int rlw = tid >> 2, cc8 = (tid & 3) * 8;   // 64 rows/pass, 2 passes/tile

    #define PW_STAGE_LOAD(ch, sbuf) do { \
        const int kk_ = (ch) * 32; \
        uint32_t base_ = sbase + (uint32_t)(sbuf) * (PW_STG3 * 2); \
        _Pragma("unroll") \
        for (int pp = 0; pp < 2; pp++) { \
            int r = rlw + pp * 64; \
            uint32_t doff = (uint32_t)(r * MP3 + cc8) * 2; \
            cp16(base_ + 0*PWT3*2 + doff, whi + (o0 + r) * C_ + kk_ + cc8); \
            cp16(base_ + 1*PWT3*2 + doff, wlo + (o0 + r) * C_ + kk_ + cc8); \
            cp16(base_ + 2*PWT3*2 + doff, tbh + r * C_ + kk_ + cc8); \
            cp16(base_ + 3*PWT3*2 + doff, tbl + r * C_ + kk_ + cc8); \
        } } while (0)

    PW_STAGE_LOAD(0, 0); CP_COMMIT;

    for (int ch = 0; ch < 8; ch++) {
        if (ch < 7) { PW_STAGE_LOAD(ch + 1, (ch + 1) & 1); CP_COMMIT; CP_WAIT1; }
        else        { CP_WAIT0; }
        __syncthreads();
        const uint32_t sb0 = sbase + (uint32_t)(ch & 1) * (PW_STG3 * 2);

        #pragma unroll
        for (int ks = 0; ks < 2; ks++) {
            const int k0 = ks * 16;
            uint32_t bh2[2][4], bl2[2][4];
            #pragma unroll
            for (int p = 0; p < 2; p++) {
                ldmx4(bh2[p], sb0 + (2*PWT3 + b_off[p] + k0) * 2);
                ldmx4(bl2[p], sb0 + (3*PWT3 + b_off[p] + k0) * 2);
            }
            #pragma unroll
            for (int mi = 0; mi < 4; mi++) {
                uint32_t ah[4], al[4];
                ldmx4(ah, sb0 + (a_off[mi] + k0) * 2);
                ldmx4(al, sb0 + (PWT3 + a_off[mi] + k0) * 2);
                #pragma unroll
                for (int ni = 0; ni < 4; ni++)
                    mma16816(d[mi][ni], ah, &bh2[ni >> 1][(ni & 1) * 2]);
                #pragma unroll
                for (int ni = 0; ni < 4; ni++)
                    mma16816(d[mi][ni], ah, &bl2[ni >> 1][(ni & 1) * 2]);
                #pragma unroll
                for (int ni = 0; ni < 4; ni++)
                    mma16816(d[mi][ni], al, &bh2[ni >> 1][(ni & 1) * 2]);
            }
        }
        __syncthreads();
    }
    #undef PW_STAGE_LOAD

    if (chain != 2) {
        #pragma unroll
        for (int mi = 0; mi < 4; mi++) {
            int o1 = o0 + m0 + mi*16 + (lane >> 2);
            float bv1 = __ldg(&bias[o1]);
            float bv2 = __ldg(&bias[o1 + 8]);
            size_t r1 = ((size_t)bh * C_ + o1) * W_;
            size_t r2 = r1 + 8 * W_;
            #pragma unroll
            for (int ni = 0; ni < 4; ni++) {
                int wc = n0 + ni*8 + (lane & 3)*2;
                __nv_bfloat162 hp, lp;
                split_bf16(d[mi][ni][0] + bv1, hp.x, lp.x);
                split_bf16(d[mi][ni][1] + bv1, hp.y, lp.y);
                *(__nv_bfloat162*)(ohi + r1 + wc) = hp;
                *(__nv_bfloat162*)(olo + r1 + wc) = lp;
                split_bf16(d[mi][ni][2] + bv2, hp.x, lp.x);
                split_bf16(d[mi][ni][3] + bv2, hp.y, lp.y);
                *(__nv_bfloat162*)(ohi + r2 + wc) = hp;
                *(__nv_bfloat162*)(olo + r2 + wc) = lp;
            }
        }
    } else {
        __syncthreads();
        float* DS = (float*)psm;        // 128 x 132 floats = 67.6KB < 80KB
        #pragma unroll
        for (int mi = 0; mi < 4; mi++) {
            int m_ = m0 + mi*16 + (lane >> 2);
            #pragma unroll
            for (int ni = 0; ni < 4; ni++) {
                int n_ = n0 + ni*8 + (lane & 3)*2;
                DS[n_*132 + m_]         = d[mi][ni][0];
                DS[(n_+1)*132 + m_]     = d[mi][ni][1];
                DS[n_*132 + m_ + 8]     = d[mi][ni][2];
                DS[(n_+1)*132 + m_ + 8] = d[mi][ni][3];
            }
        }
        __syncthreads();
        for (int i = tid; i < 128*32; i += 256) {
            int w = i >> 5, o4 = (i & 31) * 4;
            float4 v = *(float4*)&DS[w*132 + o4];
            float4 bv = *(const float4*)&bias[o0 + o4];
            size_t idx = ((size_t)bh * W_ + w) * C_ + o0 + o4;
            __nv_bfloat162 h01, h23, l01, l23;
            split_bf16(v.x + bv.x, h01.x, l01.x);
            split_bf16(v.y + bv.y, h01.y, l01.y);
            split_bf16(v.z + bv.z, h23.x, l23.x);
            split_bf16(v.w + bv.w, h23.y, l23.y);
            *(__nv_bfloat162*)(ohi + idx)     = h01;
            *(__nv_bfloat162*)(ohi + idx + 2) = h23;
            *(__nv_bfloat162*)(olo + idx)     = l01;
            *(__nv_bfloat162*)(olo + idx + 2) = l23;
        }
    }
}

// ---------------------------------------------------------------------------
// Attention, 2 CTAs/SM (unchanged from R13).
// ---------------------------------------------------------------------------
#define ATR 64
#define AMP 136
#define AQHI 0
#define AQLO (ATR*AMP)
#define AKVHI (2*ATR*AMP)
#define AKVLO (3*ATR*AMP)
#define APHI (4*ATR*AMP)
#define APLO (5*ATR*AMP)
#define APMX (6*ATR*AMP)
#define ATT_SMEM (6*ATR*AMP*2 + 1088)

__global__ __launch_bounds__(256, 2) void attn_mma_kernel(
    const __nv_bfloat16* __restrict__ qhi, const __nv_bfloat16* __restrict__ qlo,
    const __nv_bfloat16* __restrict__ khi, const __nv_bfloat16* __restrict__ klo,
    const __nv_bfloat16* __restrict__ vhi, const __nv_bfloat16* __restrict__ vlo,
    float* __restrict__ out)
{
    extern __shared__ char smraw[];
    const uint32_t sb = saddr(smraw);
    float* pm = (float*)(smraw + (size_t)APMX * 2);
    float* ps = pm + 128;
    const int r0 = blockIdx.x * ATR;
    const int h = blockIdx.y, b = blockIdx.z;
    const int bh = b * H_ + h;
    const size_t bho = (size_t)bh * (C_ * W_);
    const int tid = threadIdx.x;
    const int wid = tid >> 5, lane = tid & 31;
    const int m0 = (wid >> 1) * 16;
    const int nh = wid & 1;
    const float scale = 0.17677669529663687f;

    const int a_off = (m0 + (lane & 15)) * AMP + (lane >> 4) * 8;
    int b_off[2];
    {
        int tl = lane >> 3;
        #pragma unroll
        for (int p = 0; p < 2; p++)
            b_off[p] = (nh*32 + p*16 + (tl >> 1)*8 + (lane & 7)) * AMP + (tl & 1) * 8;
    }
    const int ra = m0 + (lane >> 2);
    const int rb = ra + 8;
    const int pcol0 = (lane & 3) * 2;

    const int rl = tid >> 4, c8 = (tid & 15) * 8;
    #define ALOAD(dstbase, src, rlen, roff, coff) do { \
        _Pragma("unroll") \
        for (int j = 0; j < 4; j++) { \
            int r = rl + j * 16; \
            cp16(sb + ((dstbase) + r * AMP + c8) * 2, \
                 (src) + ((size_t)((roff) + r)) * (rlen) + (coff) + c8); \
        } } while (0)

    #define GEMM_PIECE(acc, abase, p) do { \
        float* s4 = &acc[(p)*4][0]; \
        _Pragma("unroll") \
        for (int kw = 0; kw < 8; kw++) { \
            uint32_t fh[4], fl[4]; \
            ldmx4(fh, sb + ((abase) + a_off + kw*16) * 2); \
            ldmx4(fl, sb + ((abase) + ATR*AMP + a_off + kw*16) * 2); \
            uint32_t bh0[4], bh1[4], bl0[4], bl1[4]; \
            ldmx4(bh0, sb + (AKVHI + b_off[0] + kw*16) * 2); \
            ldmx4(bh1, sb + (AKVHI + b_off[1] + kw*16) * 2); \
            ldmx4(bl0, sb + (AKVLO + b_off[0] + kw*16) * 2); \
            ldmx4(bl1, sb + (AKVLO + b_off[1] + kw*16) * 2); \
            mma16816(s4+0,  fh, &bh0[0]); mma16816(s4+4,  fh, &bh0[2]); \
            mma16816(s4+8,  fh, &bh1[0]); mma16816(s4+12, fh, &bh1[2]); \
            mma16816(s4+0,  fh, &bl0[0]); mma16816(s4+4,  fh, &bl0[2]); \
            mma16816(s4+8,  fh, &bl1[0]); mma16816(s4+12, fh, &bl1[2]); \
            mma16816(s4+0,  fl, &bh0[0]); mma16816(s4+4,  fl, &bh0[2]); \
            mma16816(s4+8,  fl, &bh1[0]); mma16816(s4+12, fl, &bh1[2]); \
        } } while (0)

    float o[8][4];
    #pragma unroll
    for (int nt = 0; nt < 8; nt++) { o[nt][0]=0.f; o[nt][1]=0.f; o[nt][2]=0.f; o[nt][3]=0.f; }
    float m_a = -1e30f, m_b = -1e30f, l_a = 0.f, l_b = 0.f;

    ALOAD(AQHI,  qhi + bho, W_, r0, 0);
    ALOAD(AQLO,  qlo + bho, W_, r0, 0);
    ALOAD(AKVHI, khi + bho, W_, 0, 0);
    ALOAD(AKVLO, klo + bho, W_, 0, 0);
    CP_COMMIT; CP_WAIT0; __syncthreads();

    for (int dt = 0; dt < 2; dt++) {
        float s[8][4];
        #pragma unroll
        for (int nt = 0; nt < 8; nt++) { s[nt][0]=0.f; s[nt][1]=0.f; s[nt][2]=0.f; s[nt][3]=0.f; }

        GEMM_PIECE(s, AQHI, 0);
        __syncthreads();
        ALOAD(AKVHI, khi + bho, W_, dt*128 + 64, 0);
        ALOAD(AKVLO, klo + bho, W_, dt*128 + 64, 0);
        CP_COMMIT; CP_WAIT0; __syncthreads();
        GEMM_PIECE(s, AQHI, 1);
        __syncthreads();
        ALOAD(AKVHI, vhi + bho, C_, 0, dt*128);
        ALOAD(AKVLO, vlo + bho, C_, 0, dt*128);
        CP_COMMIT;

        #pragma unroll
        for (int nt = 0; nt < 8; nt++) {
            s[nt][0] *= scale; s[nt][1] *= scale; s[nt][2] *= scale; s[nt][3] *= scale;
        }
        float mc_a = -1e30f, mc_b = -1e30f;
        #pragma unroll
        for (int nt = 0; nt < 8; nt++) {
            mc_a = fmaxf(mc_a, fmaxf(s[nt][0], s[nt][1]));
            mc_b = fmaxf(mc_b, fmaxf(s[nt][2], s[nt][3]));
        }
        mc_a = fmaxf(mc_a, __shfl_xor_sync(0xffffffffu, mc_a, 1));
        mc_a = fmaxf(mc_a, __shfl_xor_sync(0xffffffffu, mc_a, 2));
        mc_b = fmaxf(mc_b, __shfl_xor_sync(0xffffffffu, mc_b, 1));
        mc_b = fmaxf(mc_b, __shfl_xor_sync(0xffffffffu, mc_b, 2));
        if ((lane & 3) == 0) { pm[nh*64 + ra] = mc_a; pm[nh*64 + rb] = mc_b; }
        __syncthreads();
        float m_na = fmaxf(m_a, fmaxf(mc_a, pm[(nh^1)*64 + ra]));
        float m_nb = fmaxf(m_b, fmaxf(mc_b, pm[(nh^1)*64 + rb]));
        float ca = __expf(m_a - m_na), cb = __expf(m_b - m_nb);
        float la_c = 0.f, lb_c = 0.f;
        #pragma unroll
        for (int nt = 0; nt < 8; nt++) {
            float e0 = __expf(s[nt][0] - m_na), e1 = __expf(s[nt][1] - m_na);
            float e2 = __expf(s[nt][2] - m_nb), e3 = __expf(s[nt][3] - m_nb);
            la_c += e0 + e1; lb_c += e2 + e3;
            int col = (nt >> 2)*64 + nh*32 + (nt & 3)*8 + pcol0;
            __nv_bfloat162 hp, lp;
            split_bf16(e0, hp.x, lp.x); split_bf16(e1, hp.y, lp.y);
            *(__nv_bfloat162*)(smraw + (APHI + ra*AMP + col)*2) = hp;
            *(__nv_bfloat162*)(smraw + (APLO + ra*AMP + col)*2) = lp;
            split_bf16(e2, hp.x, lp.x); split_bf16(e3, hp.y, lp.y);
            *(__nv_bfloat162*)(smraw + (APHI + rb*AMP + col)*2) = hp;
            *(__nv_bfloat162*)(smraw + (APLO + rb*AMP + col)*2) = lp;
            o[nt][0] *= ca; o[nt][1] *= ca; o[nt][2] *= cb; o[nt][3] *= cb;
        }
        la_c += __shfl_xor_sync(0xffffffffu, la_c, 1);
        la_c += __shfl_xor_sync(0xffffffffu, la_c, 2);
        lb_c += __shfl_xor_sync(0xffffffffu, lb_c, 1);
        lb_c += __shfl_xor_sync(0xffffffffu, lb_c, 2);
        if ((lane & 3) == 0) { ps[nh*64 + ra] = la_c; ps[nh*64 + rb] = lb_c; }
        __syncthreads();
        l_a = l_a * ca + la_c + ps[(nh^1)*64 + ra];
        l_b = l_b * cb + lb_c + ps[(nh^1)*64 + rb];
        m_a = m_na;  m_b = m_nb;
        CP_WAIT0; __syncthreads();

        GEMM_PIECE(o, APHI, 0);
        __syncthreads();
        ALOAD(AKVHI, vhi + bho, C_, 64, dt*128);
        ALOAD(AKVLO, vlo + bho, C_, 64, dt*128);
        CP_COMMIT; CP_WAIT0; __syncthreads();
        GEMM_PIECE(o, APHI, 1);

        if (dt == 0) {
            __syncthreads();
            ALOAD(AKVHI, khi + bho, W_, 128, 0);
            ALOAD(AKVLO, klo + bho, W_, 128, 0);
            CP_COMMIT; CP_WAIT0; __syncthreads();
        }
    }
    #undef ALOAD
    #undef GEMM_PIECE

    float inva = 1.f / l_a, invb = 1.f / l_b;
    __syncthreads();
    float* OS = (float*)(smraw + (size_t)APHI * 2);
    #pragma unroll
    for (int nt = 0; nt < 8; nt++) {
        int col = (nt >> 2)*64 + nh*32 + (nt & 3)*8 + pcol0;
        *(float2*)&OS[ra*132 + col] = make_float2(o[nt][0]*inva, o[nt][1]*inva);
        *(float2*)&OS[rb*132 + col] = make_float2(o[nt][2]*invb, o[nt][3]*invb);
    }
    __syncthreads();
    for (int i = tid; i < ATR*32; i += 256) {
        int r = i >> 5, w4 = (i & 31) * 4;
        *(float4*)(out + ((size_t)(b*C_ + r0 + r)*H_ + h)*W_ + w4) = *(float4*)&OS[r*132 + w4];
    }
}

// ---------------------------------------------------------------------------
extern "C" void kernel_launch(void* const* d_in, const int* in_sizes, int n_in,
                              void* d_out, int out_size)
{
    (void)in_sizes; (void)n_in; (void)out_size;
    const float* hidden = (const float*)d_in[0];
    const float* ctx    = (const float*)d_in[1];
    const float* qdw = (const float*)d_in[2];
    const float* qdb = (const float*)d_in[3];
    const float* qpw = (const float*)d_in[4];
    const float* qpb = (const float*)d_in[5];
    const float* kdw = (const float*)d_in[6];
    const float* kdb = (const float*)d_in[7];
    const float* kpw = (const float*)d_in[8];
    const float* kpb = (const float*)d_in[9];
    const float* vdw = (const float*)d_in[10];
    const float* vdb = (const float*)d_in[11];
    const float* vpw = (const float*)d_in[12];
    const float* vpb = (const float*)d_in[13];
    float* out = (float*)d_out;

    __nv_bfloat16 *whi, *wlo;
    __nv_bfloat16 *t0h, *t0l, *t1h, *t1l, *t2h, *t2l;
    __nv_bfloat16 *qhi, *qlo, *khi, *klo, *vhi, *vlo;
    cudaGetSymbolAddress((void**)&whi, g_whi);
    cudaGetSymbolAddress((void**)&wlo, g_wlo);
    cudaGetSymbolAddress((void**)&t0h, g_t0h);
    cudaGetSymbolAddress((void**)&t0l, g_t0l);
    cudaGetSymbolAddress((void**)&t1h, g_t1h);
    cudaGetSymbolAddress((void**)&t1l, g_t1l);
    cudaGetSymbolAddress((void**)&t2h, g_t2h);
    cudaGetSymbolAddress((void**)&t2l, g_t2l);
    cudaGetSymbolAddress((void**)&qhi, g_qhi);
    cudaGetSymbolAddress((void**)&qlo, g_qlo);
    cudaGetSymbolAddress((void**)&khi, g_khi);
    cudaGetSymbolAddress((void**)&klo, g_klo);
    cudaGetSymbolAddress((void**)&vhi, g_vhi);
    cudaGetSymbolAddress((void**)&vlo, g_vlo);

    cudaFuncSetAttribute(pw_mma_kernel, cudaFuncAttributeMaxDynamicSharedMemorySize, PWS_SMEM);
    cudaFuncSetAttribute(attn_mma_kernel, cudaFuncAttributeMaxDynamicSharedMemorySize, ATT_SMEM);

    dim3 dsg(C_/32, H_, 3*B_);
    dim3 pwg(6, H_, B_);
    dim3 atg(4, H_, B_);

    wsplit_kernel<<<3*C_*C_/256, 256>>>(qpw, kpw, vpw, whi, wlo);
    dwsplit_kernel<<<dsg, 256>>>(hidden, ctx, qdw, qdb, kdw, kdb, vdw, vdb,
                                 t0h, t0l, t1h, t1l, t2h, t2l);
    pw_mma_kernel<<<pwg, 256, PWS_SMEM>>>(t0h, t0l, t1h, t1l, t2h, t2l,
                                          whi, wlo, qpb, kpb, vpb,
                                          qhi, qlo, khi, klo, vhi, vlo);
    attn_mma_kernel<<<atg, 256, ATT_SMEM>>>(qhi, qlo, khi, klo, vhi, vlo, out);
}